// round 9
// baseline (speedup 1.0000x reference)
#include <cuda_runtime.h>
#include <cuda_bf16.h>
#include <cuda_fp16.h>

// Geometry
#define H 512
#define W 512
#define N_ANGLES 512
#define N_DET 736
#define N_SAMP 736

// Full-range padding: all sample coords in-bounds; outside-support reads 0.
#define PAD 272
#define PW 1056
#define PH 1056

// SMEM tile: 64x64 px of half2 pairs, pitch 68 (banks 4*y+x -> conflict-free
// for the 4x8 lane patch at axis angles; uint2-aligned staging since 68 even).
#define TILE_W 64
#define TILE_H 64
#define TPITCH 68
#define CHUNK 32

// fp16 pair image: g_pairh[y*PW+x] = half2( I[y][x], I[y][x+1] ), zero-padded.
__device__ unsigned int g_pairh[PH * PW];

// ---------------------------------------------------------------------------
__global__ void build_pairh_kernel(const float* __restrict__ xin,
                                   const float* __restrict__ rin) {
    int idx = blockIdx.x * blockDim.x + threadIdx.x;
    if (idx >= PH * PW) return;
    int yq = idx / PW;
    int xq = idx - yq * PW;
    int y = yq - PAD;
    int x = xq - PAD;

    float v0 = 0.f, v1 = 0.f;
    if (y >= 0 && y < H) {
        if (x >= 0 && x < W)         v0 = xin[y * W + x]     + rin[y * W + x];
        if (x + 1 >= 0 && x + 1 < W) v1 = xin[y * W + x + 1] + rin[y * W + x + 1];
    }
    __half2 h = __floats2half2_rn(v0, v1);
    g_pairh[idx] = *reinterpret_cast<unsigned int*>(&h);
}

__global__ void copy_reco_kernel(const float4* __restrict__ src,
                                 float4* __restrict__ dst, int n4) {
    int i = blockIdx.x * blockDim.x + threadIdx.x;
    if (i < n4) dst[i] = src[i];
}

// interval product [a0,a1] x [b0,b1]
__device__ __forceinline__ void imul(float a0, float a1, float b0, float b1,
                                     float& lo, float& hi) {
    float p1 = a0 * b0, p2 = a0 * b1, p3 = a1 * b0, p4 = a1 * b1;
    lo = fminf(fminf(p1, p2), fminf(p3, p4));
    hi = fmaxf(fmaxf(p1, p2), fmaxf(p3, p4));
}

// ---------------------------------------------------------------------------
// grid = (23, 128): blockIdx.x = 32-detector block, blockIdx.y = 4-angle group.
// block = 256 = 8 warps. warp -> angle (w&3) and det-half (w>>2)*16.
// Within a warp: lane = tq*4 + dq (tq 0..7 sample phase, dq 0..3 detector).
// dsub 0..3 selects the 4-detector subgroup; sample n = c0 + ti*8 + tq.
// ---------------------------------------------------------------------------
__global__ void __launch_bounds__(256, 5)
project_kernel(const float* __restrict__ angles, float* __restrict__ sino) {
    __shared__ unsigned int tile[TILE_H * TPITCH];

    const int lane = threadIdx.x & 31;
    const int warp = threadIdx.x >> 5;
    const int tq = lane >> 2;
    const int dq = lane & 3;

    const int a0 = blockIdx.y * 4;
    const int angle = a0 + (warp & 3);
    const int dbase = blockIdx.x * 32 + (warp >> 2) * 16;   // + ds*4 + dq

    const float theta = __ldg(&angles[angle]);
    float si, c;
    sincosf(theta, &si, &c);

    // block-uniform cos/sin intervals over the 4 actual angles
    float cmin = 1e9f, cmax = -1e9f, smn = 1e9f, smx = -1e9f;
    #pragma unroll
    for (int k = 0; k < 4; ++k) {
        float sk, ck;
        sincosf(__ldg(&angles[a0 + k]), &sk, &ck);
        cmin = fminf(cmin, ck); cmax = fmaxf(cmax, ck);
        smn = fminf(smn, sk);   smx = fmaxf(smx, sk);
    }
    cmin -= 2e-4f; cmax += 2e-4f; smn -= 2e-4f; smx += 2e-4f;

    const float sA = (float)(blockIdx.x * 32) - 367.5f;   // block s-range
    const float sB = sA + 31.0f;

    // per-(lane,dsub) chord clipping -> warp-uniform sample ranges [n0,n1)
    const float sd0 = (float)(dbase + dq) - 367.5f;
    int n0[4], n1[4];
    #pragma unroll
    for (int ds = 0; ds < 4; ++ds) {
        const float s = sd0 + (float)(4 * ds);
        const float A = fmaf(s, c, 255.5f);
        const float B = fmaf(s, si, 255.5f);
        float tlo = -368.0f, thi = 368.0f;
        if (fabsf(si) > 1e-6f) {
            float u1 = (A - 512.0f) / si, u2 = (A + 1.0f) / si;
            tlo = fmaxf(tlo, fminf(u1, u2));
            thi = fminf(thi, fmaxf(u1, u2));
        } else if (A <= -1.0f || A >= 512.0f) {
            thi = tlo;
        }
        if (fabsf(c) > 1e-6f) {
            float u1 = (-1.0f - B) / c, u2 = (512.0f - B) / c;
            tlo = fmaxf(tlo, fminf(u1, u2));
            thi = fminf(thi, fmaxf(u1, u2));
        } else if (B <= -1.0f || B >= 512.0f) {
            thi = tlo;
        }
        int i0 = max(0, __float2int_rd(tlo + 367.5f) - 1);
        int i1 = min(N_SAMP, __float2int_ru(thi + 367.5f) + 1);
        if (i1 < i0) i1 = i0;
        n0[ds] = __reduce_min_sync(0xFFFFFFFFu, i0);
        n1[ds] = __reduce_max_sync(0xFFFFFFFFu, i1);
    }

    const float tqf = (float)tq;
    const float DX = -si, DY = c;
    const float DX8 = -8.0f * si, DY8 = 8.0f * c;
    float acc[4] = {0.f, 0.f, 0.f, 0.f};

    for (int c0 = 0; c0 < N_SAMP; c0 += CHUNK) {
        // uniform chunk AABB via interval arithmetic
        const float t0i = (float)c0 - 367.5f;
        const float t1i = t0i + (float)(CHUNK - 1);
        float scn, scx, tsn, tsx, ssn, ssx, tcn, tcx;
        imul(sA, sB, cmin, cmax, scn, scx);
        imul(t0i, t1i, smn, smx, tsn, tsx);
        imul(sA, sB, smn, smx, ssn, ssx);
        imul(t0i, t1i, cmin, cmax, tcn, tcx);
        const float pxn = scn - tsx + 527.5f, pxx = scx - tsn + 527.5f;
        const float pyn = ssn + tcn + 527.5f, pyx = ssx + tcx + 527.5f;

        // skip chunks with no support overlap (block-uniform)
        if (pxx < 270.0f || pxn > 787.0f || pyx < 270.0f || pyn > 787.0f)
            continue;

        const int tx0 = min(max((__float2int_rd(pxn) - 2) & ~1, 0), PW - TILE_W);
        const int ty0 = min(max(__float2int_rd(pyn) - 2, 0), PH - TILE_H);

        __syncthreads();
        {   // cooperative stage: 64 rows x 32 uint2 (256B/row), coalesced
            const uint2* gp2 = (const uint2*)g_pairh;
            uint2* tp2 = (uint2*)tile;
            const int gbase = ty0 * (PW / 2) + (tx0 >> 1);
            #pragma unroll
            for (int i = threadIdx.x; i < TILE_H * 32; i += 256) {
                const int r = i >> 5, cc = i & 31;
                tp2[r * (TPITCH / 2) + cc] = gp2[gbase + r * (PW / 2) + cc];
            }
        }
        __syncthreads();

        const float oxf = 527.5f - (float)tx0;
        const float oyf = 527.5f - (float)ty0;

        #pragma unroll
        for (int ds = 0; ds < 4; ++ds) {
            const int a = max(n0[ds], c0);
            const int b = min(n1[ds], c0 + CHUNK);
            if (a >= b) continue;                     // warp-uniform
            const int ti0 = (a - c0) >> 3;
            const int ti1 = (b - 1 - c0) >> 3;

            const float s = sd0 + (float)(4 * ds);
            const float tb = (float)(c0 + ti0 * 8) + tqf - 367.5f;
            float px = fmaf(tb, DX, fmaf(s, c, oxf));
            float py = fmaf(tb, DY, fmaf(s, si, oyf));
            float accl = 0.0f;

            for (int ti = ti0; ti <= ti1; ++ti) {
                const float xf = floorf(px);
                const float yf = floorf(py);
                const float fx = px - xf;
                const float fy = py - yf;
                int word = __float2int_rn(fmaf(yf, (float)TPITCH, xf));
                word = min(max(word, 0), TILE_H * TPITCH - TPITCH - 2);
                const unsigned int u0 = tile[word];
                const unsigned int u1 = tile[word + TPITCH];
                const float2 f0 = __half22float2(*(const __half2*)&u0);
                const float2 f1 = __half22float2(*(const __half2*)&u1);
                const float top = fmaf(fx, f0.y - f0.x, f0.x);
                const float bot = fmaf(fx, f1.y - f1.x, f1.x);
                accl = fmaf(fy, bot - top, accl + top);
                px += DX8;
                py += DY8;
            }
            acc[ds] += accl;
        }
    }

    // reduce over tq (bits [2:4] of lane) and write
    #pragma unroll
    for (int ds = 0; ds < 4; ++ds) {
        float v = acc[ds];
        v += __shfl_xor_sync(0xFFFFFFFFu, v, 16);
        v += __shfl_xor_sync(0xFFFFFFFFu, v, 8);
        v += __shfl_xor_sync(0xFFFFFFFFu, v, 4);
        if (tq == 0)
            sino[angle * N_DET + dbase + ds * 4 + dq] = v;
    }
}

// ---------------------------------------------------------------------------
extern "C" void kernel_launch(void* const* d_in, const int* in_sizes, int n_in,
                              void* d_out, int out_size) {
    const float* xin    = (const float*)d_in[0];   // [1,512,512]
    const float* rin    = (const float*)d_in[1];   // [1,512,512]
    const float* angles = (const float*)d_in[2];   // [512]

    float* out = (float*)d_out;
    float* sino_out = out;                         // [1,512,736]
    float* reco_out = out + N_ANGLES * N_DET;      // [1,512,512]

    {
        int total = PH * PW;
        int threads = 256;
        int blocks = (total + threads - 1) / threads;
        build_pairh_kernel<<<blocks, threads>>>(xin, rin);
    }
    {
        int n4 = (H * W) / 4;
        int threads = 256;
        int blocks = (n4 + threads - 1) / threads;
        copy_reco_kernel<<<blocks, threads>>>((const float4*)rin, (float4*)reco_out, n4);
    }
    {
        dim3 grid(N_DET / 32, N_ANGLES / 4);       // (23, 128)
        project_kernel<<<grid, 256>>>(angles, sino_out);
    }
}

// round 11
// speedup vs baseline: 1.3942x; 1.3942x over previous
#include <cuda_runtime.h>
#include <cuda_bf16.h>
#include <cuda_fp16.h>

// Geometry
#define H 512
#define W 512
#define N_ANGLES 512
#define N_DET 736
#define N_SAMP 736

// Full-range padding: all sample coords in-bounds; outside-support reads 0.
#define PAD 272
#define PW 1056            // divisible by 8
#define PH 1056            // divisible by 4
#define TWX (PW / 8)       // 132 x-tiles per tile-row

// fp16 pair image, 4B/px, tiled: one 128B line = 8(x) x 4(y) px block.
// element (y,x): idx = ((y>>2)*TWX + (x>>3))*32 + (y&3)*8 + (x&7)
// value = half2( I[y][x], I[y][x+1] ) on the zero-padded field.
__device__ unsigned int g_pairh[PH * PW];

// y+1 step inside/across tile: +8 within tile, +(TWX*32 - 24) across
#define YSTEP_IN 8
#define YSTEP_X  (TWX * 32 - 24)   // 4200

__device__ __forceinline__ int pair_idx(int y, int x) {
    return (((y >> 2) * TWX + (x >> 3)) << 5) + ((y & 3) << 3) + (x & 7);
}

// ---------------------------------------------------------------------------
__global__ void build_pairh_kernel(const float* __restrict__ xin,
                                   const float* __restrict__ rin) {
    int idx = blockIdx.x * blockDim.x + threadIdx.x;
    if (idx >= PH * PW) return;
    int yq = idx / PW;
    int xq = idx - yq * PW;
    int y = yq - PAD;
    int x = xq - PAD;

    float v0 = 0.f, v1 = 0.f;
    if (y >= 0 && y < H) {
        if (x >= 0 && x < W)         v0 = xin[y * W + x]     + rin[y * W + x];
        if (x + 1 >= 0 && x + 1 < W) v1 = xin[y * W + x + 1] + rin[y * W + x + 1];
    }
    __half2 h = __floats2half2_rn(v0, v1);
    g_pairh[pair_idx(yq, xq)] = *reinterpret_cast<unsigned int*>(&h);
}

__global__ void copy_reco_kernel(const float4* __restrict__ src,
                                 float4* __restrict__ dst, int n4) {
    int i = blockIdx.x * blockDim.x + threadIdx.x;
    if (i < n4) dst[i] = src[i];
}

// ---------------------------------------------------------------------------
// grid = (23, 256): blockIdx.y = angle PAIR, blockIdx.x = 32-detector block.
// block = 256 = 8 warps; each warp: 2 angles x 4 detectors x 4 t-phases.
// lane = aq*16 + tq*4 + dq. Lane samples t-index n = 4*it + tq.
// ---------------------------------------------------------------------------
__global__ void __launch_bounds__(256, 6)
project_kernel(const float* __restrict__ angles, float* __restrict__ sino) {
    const int lane = threadIdx.x & 31;
    const int warp = threadIdx.x >> 5;
    const int aq = lane >> 4;          // 0..1
    const int tq = (lane >> 2) & 3;    // 0..3
    const int dq = lane & 3;           // 0..3

    const int angle = blockIdx.y * 2 + aq;
    const int d = blockIdx.x * 32 + warp * 4 + dq;

    const float theta = __ldg(&angles[angle]);
    float si, c;
    sincosf(theta, &si, &c);

    const float s = (float)d - 367.5f;
    const float CTR = 255.5f + (float)PAD;        // 527.5

    // px(n) = s*c - (n - 367.5)*si + CTR, n = 4*it + tq
    const float BX = s * c + (367.5f - (float)tq) * si + CTR;
    const float BY = s * si - (367.5f - (float)tq) * c + CTR;
    const float DX = -4.0f * si;
    const float DY = 4.0f * c;

    // ---- exact chord clipping (unpadded coords), per lane ----
    const float A = s * c + 255.5f;
    const float B = s * si + 255.5f;
    float tlo = -368.0f, thi = 368.0f;
    if (fabsf(si) > 1e-6f) {
        float u1 = (A - 512.0f) / si, u2 = (A + 1.0f) / si;
        tlo = fmaxf(tlo, fminf(u1, u2));
        thi = fminf(thi, fmaxf(u1, u2));
    } else if (A <= -1.0f || A >= 512.0f) {
        thi = tlo;
    }
    if (fabsf(c) > 1e-6f) {
        float u1 = (-1.0f - B) / c, u2 = (512.0f - B) / c;
        tlo = fmaxf(tlo, fminf(u1, u2));
        thi = fminf(thi, fmaxf(u1, u2));
    } else if (B <= -1.0f || B >= 512.0f) {
        thi = tlo;
    }
    int it0 = __float2int_rd((tlo + 367.5f - (float)tq) * 0.25f);
    int it1 = __float2int_ru((thi + 367.5f - (float)tq) * 0.25f) + 1;
    it0 = min(max(it0, 0), N_SAMP / 4);
    it1 = min(max(it1, it0), N_SAMP / 4);

    const int wit0 = __reduce_min_sync(0xFFFFFFFFu, it0);
    const int wit1 = __reduce_max_sync(0xFFFFFFFFu, it1);

    float px = BX + (float)wit0 * DX;
    float py = BY + (float)wit0 * DY;
    float acc = 0.0f;

#pragma unroll 4
    for (int it = wit0; it < wit1; ++it) {
        const int xi = __float2int_rd(px);       // coords always positive
        const int yi = __float2int_rd(py);
        const float fx = px - (float)xi;
        const float fy = py - (float)yi;
        const int yr = yi & 3;
        const int idx = (((yi >> 2) * TWX + (xi >> 3)) << 5)
                        + (yr << 3) + (xi & 7);
        const int idx2 = idx + ((yr == 3) ? YSTEP_X : YSTEP_IN);
        const unsigned int u0 = __ldg(&g_pairh[idx]);   // (v00, v01)
        const unsigned int u1 = __ldg(&g_pairh[idx2]);  // (v10, v11)
        const float2 f0 = __half22float2(*reinterpret_cast<const __half2*>(&u0));
        const float2 f1 = __half22float2(*reinterpret_cast<const __half2*>(&u1));
        const float top = fmaf(fx, f0.y - f0.x, f0.x);
        const float bot = fmaf(fx, f1.y - f1.x, f1.x);
        acc = fmaf(fy, bot - top, acc + top);
        px += DX;
        py += DY;
    }

    // reduce over tq (lane bits [2:3])
    acc += __shfl_xor_sync(0xFFFFFFFFu, acc, 8);
    acc += __shfl_xor_sync(0xFFFFFFFFu, acc, 4);

    if (tq == 0) {
        sino[angle * N_DET + d] = acc;   // STEP = 1.0
    }
}

// ---------------------------------------------------------------------------
extern "C" void kernel_launch(void* const* d_in, const int* in_sizes, int n_in,
                              void* d_out, int out_size) {
    const float* xin    = (const float*)d_in[0];   // [1,512,512]
    const float* rin    = (const float*)d_in[1];   // [1,512,512]
    const float* angles = (const float*)d_in[2];   // [512]

    float* out = (float*)d_out;
    float* sino_out = out;                         // [1,512,736]
    float* reco_out = out + N_ANGLES * N_DET;      // [1,512,512]

    {
        int total = PH * PW;
        int threads = 256;
        int blocks = (total + threads - 1) / threads;
        build_pairh_kernel<<<blocks, threads>>>(xin, rin);
    }
    {
        int n4 = (H * W) / 4;
        int threads = 256;
        int blocks = (n4 + threads - 1) / threads;
        copy_reco_kernel<<<blocks, threads>>>((const float4*)rin, (float4*)reco_out, n4);
    }
    {
        dim3 grid(N_DET / 32, N_ANGLES / 2);       // (23, 256)
        project_kernel<<<grid, 256>>>(angles, sino_out);
    }
}